// round 10
// baseline (speedup 1.0000x reference)
#include <cuda_runtime.h>
#include <cstdint>
#include <cstddef>

#define NC 10
#define DD 512
#define D4 128          // DD/4
#define SEG_BLOCKS 296
#define SEG_GROUPS (SEG_BLOCKS * 4)
#define SEG_SMEM (4 * NC * D4 * 16)   // 81920 bytes

// k_logits bulk-streamed pipeline geometry
#define CHUNK_ROWS 32
#define ROW_PAD    2112               // 2048 + 64B pad: e-loads 2-phase, not 4
#define STAGE_BYTES (CHUNK_ROWS * ROW_PAD)        // 67584
#define LOG_SMEM   (2 * STAGE_BYTES)              // 135168 dynamic
#define SP_STRIDE  2112               // padded prototype row: p-loads 1-phase
#define LOG_GRID   152

typedef unsigned long long ull;

// Scratch (no cudaMalloc allowed)
__device__ float4 g_part4[SEG_BLOCKS * NC * D4];   // 6.06 MB partial sums
__device__ int    g_cnt_part[SEG_BLOCKS * NC];
__device__ float4 g_sums4[NC * D4];
__device__ float4 g_proto4[NC * D4];
__device__ float  g_sqp[NC];
__device__ float  g_loss;

static __device__ __forceinline__ ull fma2(ull a, ull b, ull c) {
    ull d;
    asm("fma.rn.f32x2 %0, %1, %2, %3;" : "=l"(d) : "l"(a), "l"(b), "l"(c));
    return d;
}
static __device__ __forceinline__ float u64_sum2(ull v) {
    float lo, hi;
    asm("mov.b64 {%0,%1}, %2;" : "=f"(lo), "=f"(hi) : "l"(v));
    return lo + hi;
}
static __device__ __forceinline__ uint32_t smem_u32(const void* p) {
    uint32_t a;
    asm("{ .reg .u64 t; cvta.to.shared.u64 t, %1; cvt.u32.u64 %0, t; }"
        : "=r"(a) : "l"(p));
    return a;
}
static __device__ __forceinline__ void cp_async16(uint32_t dst, const void* src) {
    asm volatile("cp.async.cg.shared.global [%0], [%1], 16;"
                 :: "r"(dst), "l"(src));
}

// ---------------------------------------------------------------------------
// K1: segment sums (R9 version: 4 replicas + depth-1 prefetch, 5.1 TB/s).
// ---------------------------------------------------------------------------
__global__ __launch_bounds__(512) void k_segsum(const float4* __restrict__ E4,
                                                const int* __restrict__ labels,
                                                int nrows) {
    extern __shared__ float4 sm4[];            // [4][NC][D4]
    __shared__ int scnt[NC];
    const int g = threadIdx.x >> 7;
    const int t = threadIdx.x & 127;
    float4* rep = sm4 + g * (NC * D4);

    if (threadIdx.x < NC) scnt[threadIdx.x] = 0;
#pragma unroll
    for (int c = 0; c < NC; c++) rep[c * D4 + t] = make_float4(0.f, 0.f, 0.f, 0.f);
    __syncthreads();

    const int  gid    = blockIdx.x * 4 + g;
    const long stride = (long)SEG_GROUPS * 4;
    long r = (long)gid * 4;

    int4  lab = make_int4(0, 0, 0, 0);
    float4 v0, v1, v2, v3;
    bool have = (r + 4 <= nrows);
    if (have) {
        lab = *(const int4*)(labels + r);
        v0 = E4[(size_t)(r + 0) * D4 + t];
        v1 = E4[(size_t)(r + 1) * D4 + t];
        v2 = E4[(size_t)(r + 2) * D4 + t];
        v3 = E4[(size_t)(r + 3) * D4 + t];
    }
    while (have) {
        const long rn   = r + stride;
        const bool haven = (rn + 4 <= nrows);
        int4  labn = lab;
        float4 n0 = v0, n1 = v1, n2 = v2, n3 = v3;
        if (haven) {
            labn = *(const int4*)(labels + rn);
            n0 = E4[(size_t)(rn + 0) * D4 + t];
            n1 = E4[(size_t)(rn + 1) * D4 + t];
            n2 = E4[(size_t)(rn + 2) * D4 + t];
            n3 = E4[(size_t)(rn + 3) * D4 + t];
        }
        if (t == 0) {
            atomicAdd(&scnt[lab.x], 1); atomicAdd(&scnt[lab.y], 1);
            atomicAdd(&scnt[lab.z], 1); atomicAdd(&scnt[lab.w], 1);
        }
        float4* p;
        p = &rep[lab.x * D4 + t];
        { float4 a = *p; a.x += v0.x; a.y += v0.y; a.z += v0.z; a.w += v0.w; *p = a; }
        p = &rep[lab.y * D4 + t];
        { float4 a = *p; a.x += v1.x; a.y += v1.y; a.z += v1.z; a.w += v1.w; *p = a; }
        p = &rep[lab.z * D4 + t];
        { float4 a = *p; a.x += v2.x; a.y += v2.y; a.z += v2.z; a.w += v2.w; *p = a; }
        p = &rep[lab.w * D4 + t];
        { float4 a = *p; a.x += v3.x; a.y += v3.y; a.z += v3.z; a.w += v3.w; *p = a; }
        r = rn; have = haven;
        lab = labn; v0 = n0; v1 = n1; v2 = n2; v3 = n3;
    }
    if (r < nrows) {
        for (long rr = r; rr < nrows && rr < r + 4; rr++) {
            int lj = labels[rr];
            float4 v = E4[(size_t)rr * D4 + t];
            if (t == 0) atomicAdd(&scnt[lj], 1);
            float4* p = &rep[lj * D4 + t];
            float4 a = *p; a.x += v.x; a.y += v.y; a.z += v.z; a.w += v.w; *p = a;
        }
    }
    __syncthreads();

    for (int i = threadIdx.x; i < NC * D4; i += 512) {
        float4 a = sm4[i];
        float4 b = sm4[NC * D4 + i];
        float4 c = sm4[2 * NC * D4 + i];
        float4 d = sm4[3 * NC * D4 + i];
        a.x += b.x + c.x + d.x;
        a.y += b.y + c.y + d.y;
        a.z += b.z + c.z + d.z;
        a.w += b.w + c.w + d.w;
        g_part4[blockIdx.x * (NC * D4) + i] = a;
    }
    if (threadIdx.x < NC)
        g_cnt_part[blockIdx.x * NC + threadIdx.x] = scnt[threadIdx.x];
}

// ---------------------------------------------------------------------------
// K2: reduce partials -> g_sums4.
// ---------------------------------------------------------------------------
__global__ __launch_bounds__(128) void k_reduce() {
    const int i  = blockIdx.x * 32 + (threadIdx.x >> 2);
    const int ps = threadIdx.x & 3;
    float4 acc = make_float4(0.f, 0.f, 0.f, 0.f);
#pragma unroll 8
    for (int p = ps; p < SEG_BLOCKS; p += 4) {
        float4 v = g_part4[p * (NC * D4) + i];
        acc.x += v.x; acc.y += v.y; acc.z += v.z; acc.w += v.w;
    }
#pragma unroll
    for (int st = 1; st <= 2; st <<= 1) {
        acc.x += __shfl_xor_sync(0xFFFFFFFFu, acc.x, st);
        acc.y += __shfl_xor_sync(0xFFFFFFFFu, acc.y, st);
        acc.z += __shfl_xor_sync(0xFFFFFFFFu, acc.z, st);
        acc.w += __shfl_xor_sync(0xFFFFFFFFu, acc.w, st);
    }
    if (ps == 0) g_sums4[i] = acc;
}

// ---------------------------------------------------------------------------
// K3: counts -> prototypes -> ||p||^2 ; zero g_loss.
// ---------------------------------------------------------------------------
__global__ __launch_bounds__(512) void k_proto() {
    __shared__ float sinv[NC];
    const int tid = threadIdx.x, lane = tid & 31, w = tid >> 5;
    if (w < NC) {
        int s = 0;
        for (int p = lane; p < SEG_BLOCKS; p += 32) s += g_cnt_part[p * NC + w];
#pragma unroll
        for (int st = 16; st >= 1; st >>= 1) s += __shfl_xor_sync(0xFFFFFFFFu, s, st);
        if (lane == 0) sinv[w] = 1.0f / (float)s;
    }
    if (tid == 0) g_loss = 0.f;
    __syncthreads();
    const float* gs = (const float*)g_sums4;
    float*       gp = (float*)g_proto4;
#pragma unroll
    for (int c = 0; c < NC; c++) gp[c * DD + tid] = gs[c * DD + tid] * sinv[c];
    __syncthreads();
    if (w < NC) {
        const float* p = gp + w * DD;
        float acc = 0.f;
        for (int j = lane; j < DD; j += 32) acc = fmaf(p[j], p[j], acc);
#pragma unroll
        for (int st = 16; st >= 1; st >>= 1) acc += __shfl_xor_sync(0xFFFFFFFFu, acc, st);
        if (lane == 0) g_sqp[w] = acc;
    }
}

// ---------------------------------------------------------------------------
// K4: logits — bulk-streamed whole-row double-buffer pipeline.
// 256 threads = 1 block/SM. Chunks of 32 contiguous rows (64KB) staged by
// cp.async (all 256 threads, 256B each) into 2 padded smem stages; compute
// reads rows only from smem. 64KB always in flight per SM. Groups: 8 lanes
// (4 dimq x 2 class-halves) own one row each; 32 groups = 32 rows/chunk.
// Bank math: row pad 64B -> e warp-load 2-phase (256B min); proto stride
// 2112 -> 8x16B distinct bank-quads -> 1-phase p loads.
// ---------------------------------------------------------------------------
__global__ __launch_bounds__(256, 1) void k_logits(const float* __restrict__ E,
                                                   const int* __restrict__ labels,
                                                   float* __restrict__ out,
                                                   int nrows) {
    extern __shared__ char dynbuf[];           // 2 * STAGE_BYTES
    __shared__ char   spbuf[NC * SP_STRIDE];   // padded prototypes (21120B)
    __shared__ float  ssqp[NC];
    __shared__ float  sloss;

    const int tid = threadIdx.x;
    // Load prototypes into padded layout.
    for (int i = tid; i < NC * D4; i += 256) {
        int c = i / D4, f = i % D4;
        *(float4*)(spbuf + c * SP_STRIDE + f * 16) = g_proto4[i];
    }
    if (tid < NC) ssqp[tid] = g_sqp[tid];
    if (tid == 0) sloss = 0.f;

    const int warp = tid >> 5;
    const int lane = tid & 31;
    const int dimq = lane & 3;
    const int ch   = (lane >> 2) & 1;
    const int gg   = lane >> 3;                 // group within warp
    const unsigned gmask = 0xFFu << (gg * 8);
    const int trow = warp * 4 + gg;             // this thread's row in chunk

    // Staging map: thread covers bytes [tid*256, tid*256+256) of the 64KB
    // chunk = row (tid>>3), 256B piece (tid&7).
    const int srow  = tid >> 3;
    const int spick = tid & 7;
    const uint32_t sbase = smem_u32(dynbuf);
    const uint32_t sdst  = sbase + srow * ROW_PAD + spick * 256;

    const long nchunks = ((long)nrows + CHUNK_ROWS - 1) / CHUNK_ROWS;
    const long c0 = blockIdx.x;

    __syncthreads();   // spbuf/ssqp/sloss ready

    // Prologue: stage chunk c0 into stage 0.
    if (c0 < nchunks) {
        long gr = c0 * CHUNK_ROWS + srow;
        if (gr > nrows - 1) gr = nrows - 1;
        const float* src = E + (size_t)gr * DD + spick * 64;
#pragma unroll
        for (int j = 0; j < 16; j++) cp_async16(sdst + j * 16, src + j * 4);
    }
    asm volatile("cp.async.commit_group;");

    float lvsum = 0.f;
    int stage = 0;
    for (long chunk = c0; chunk < nchunks; chunk += LOG_GRID) {
        // Stage next chunk into the other buffer (its compute finished last
        // iteration; the trailing __syncthreads ordered it).
        const long nxt = chunk + LOG_GRID;
        if (nxt < nchunks) {
            long gr = nxt * CHUNK_ROWS + srow;
            if (gr > nrows - 1) gr = nrows - 1;
            const float* src = E + (size_t)gr * DD + spick * 64;
            uint32_t dst = sdst + (stage ^ 1) * STAGE_BYTES;
#pragma unroll
            for (int j = 0; j < 16; j++) cp_async16(dst + j * 16, src + j * 4);
        }
        asm volatile("cp.async.commit_group;");   // always: keeps group count in step
        asm volatile("cp.async.wait_group 1;");   // current chunk's group done
        __syncthreads();

        // ---- Compute this chunk (1 row per 8-lane group). ----
        const char* erow = dynbuf + stage * STAGE_BYTES + trow * ROW_PAD;
        const char* pch  = spbuf + (ch * 5) * SP_STRIDE;

        ull dot0 = 0, dot1 = 0, dot2 = 0, dot3 = 0, dot4 = 0, sq = 0;
#pragma unroll 4
        for (int k = 0; k < 32; k++) {
            const int off = k * 64 + dimq * 16;
            ulonglong2 v = *(const ulonglong2*)(erow + off);
            sq = fma2(v.x, v.x, sq); sq = fma2(v.y, v.y, sq);
            ulonglong2 p0 = *(const ulonglong2*)(pch + 0 * SP_STRIDE + off);
            ulonglong2 p1 = *(const ulonglong2*)(pch + 1 * SP_STRIDE + off);
            ulonglong2 p2 = *(const ulonglong2*)(pch + 2 * SP_STRIDE + off);
            ulonglong2 p3 = *(const ulonglong2*)(pch + 3 * SP_STRIDE + off);
            ulonglong2 p4 = *(const ulonglong2*)(pch + 4 * SP_STRIDE + off);
            dot0 = fma2(v.x, p0.x, dot0); dot0 = fma2(v.y, p0.y, dot0);
            dot1 = fma2(v.x, p1.x, dot1); dot1 = fma2(v.y, p1.y, dot1);
            dot2 = fma2(v.x, p2.x, dot2); dot2 = fma2(v.y, p2.y, dot2);
            dot3 = fma2(v.x, p3.x, dot3); dot3 = fma2(v.y, p3.y, dot3);
            dot4 = fma2(v.x, p4.x, dot4); dot4 = fma2(v.y, p4.y, dot4);
        }

        // ---- Epilogue for this row. ----
        const long row   = chunk * CHUNK_ROWS + trow;
        const bool valid = (row < nrows);
        const long rowc  = valid ? row : (nrows - 1);

        float sqe = u64_sum2(sq);
        sqe += __shfl_xor_sync(gmask, sqe, 1);
        sqe += __shfl_xor_sync(gmask, sqe, 2);

        float l[5], df[5] = { u64_sum2(dot0), u64_sum2(dot1), u64_sum2(dot2),
                              u64_sum2(dot3), u64_sum2(dot4) };
        float m5 = -1e30f;
#pragma unroll
        for (int c = 0; c < 5; c++) {
            float d = df[c];
            d += __shfl_xor_sync(gmask, d, 1);
            d += __shfl_xor_sync(gmask, d, 2);
            float d2 = sqe + ssqp[ch * 5 + c] - 2.0f * d;
            float lg = -fmaxf(d2, 0.0f);
            l[c] = lg;
            m5 = fmaxf(m5, lg);
        }
        float m = fmaxf(m5, __shfl_xor_sync(gmask, m5, 4));
        float se5 = 0.f;
#pragma unroll
        for (int c = 0; c < 5; c++) se5 += __expf(l[c] - m);
        float se = se5 + __shfl_xor_sync(gmask, se5, 4);

        const int lab = labels[rowc];
        float lsel5 = 0.f;
#pragma unroll
        for (int c = 0; c < 5; c++)
            if (ch * 5 + c == lab) lsel5 = l[c];
        float lsel = lsel5 + __shfl_xor_sync(gmask, lsel5, 4);

        if (dimq == 0 && valid) {
            float* o = out + 1 + (size_t)rowc * NC + ch * 5;
#pragma unroll
            for (int c = 0; c < 5; c++) o[c] = l[c];
        }
        if (dimq == 0 && ch == 0 && valid)
            lvsum += m + __logf(se) - lsel;

        __syncthreads();   // whole block done with this stage before reuse
        stage ^= 1;
    }

    // Loss: warp reduce -> smem -> global (once per block).
#pragma unroll
    for (int st = 16; st >= 1; st >>= 1)
        lvsum += __shfl_xor_sync(0xFFFFFFFFu, lvsum, st);
    if (lane == 0) atomicAdd(&sloss, lvsum);
    __syncthreads();
    if (tid == 0) atomicAdd(&g_loss, sloss);
}

// ---------------------------------------------------------------------------
// K5: finalize loss
// ---------------------------------------------------------------------------
__global__ void k_final(float* __restrict__ out, int nrows) {
    out[0] = g_loss * (1.0f / (float)nrows);
}

extern "C" void kernel_launch(void* const* d_in, const int* in_sizes, int n_in,
                              void* d_out, int out_size) {
    const float* E      = (const float*)d_in[0];
    const int*   labels = (const int*)d_in[1];
    float*       out    = (float*)d_out;
    const int nrows = in_sizes[1];   // 131072

    cudaFuncSetAttribute(k_segsum, cudaFuncAttributeMaxDynamicSharedMemorySize,
                         SEG_SMEM);
    cudaFuncSetAttribute(k_logits, cudaFuncAttributeMaxDynamicSharedMemorySize,
                         LOG_SMEM);

    k_segsum<<<SEG_BLOCKS, 512, SEG_SMEM>>>((const float4*)E, labels, nrows);
    k_reduce<<<40, 128>>>();
    k_proto<<<1, 512>>>();
    k_logits<<<LOG_GRID, 256, LOG_SMEM>>>(E, labels, out, nrows);
    k_final<<<1, 1>>>(out, nrows);
}

// round 11
// speedup vs baseline: 1.2716x; 1.2716x over previous
#include <cuda_runtime.h>
#include <cstdint>
#include <cstddef>

#define NC 10
#define DD 512
#define D4 128          // DD/4
#define SEG_BLOCKS 296
#define SEG_GROUPS (SEG_BLOCKS * 4)
#define SEG_SMEM (4 * NC * D4 * 16)   // 81920 bytes

typedef unsigned long long ull;

// Scratch (no cudaMalloc allowed)
__device__ float4 g_part4[SEG_BLOCKS * NC * D4];   // 6.06 MB partial sums
__device__ int    g_cnt_part[SEG_BLOCKS * NC];
__device__ float4 g_sums4[NC * D4];
__device__ float4 g_proto4[NC * D4];
__device__ float  g_sqp[NC];
__device__ float  g_loss;

static __device__ __forceinline__ ull fma2(ull a, ull b, ull c) {
    ull d;
    asm("fma.rn.f32x2 %0, %1, %2, %3;" : "=l"(d) : "l"(a), "l"(b), "l"(c));
    return d;
}
static __device__ __forceinline__ float u64_sum2(ull v) {
    float lo, hi;
    asm("mov.b64 {%0,%1}, %2;" : "=f"(lo), "=f"(hi) : "l"(v));
    return lo + hi;
}

// ---------------------------------------------------------------------------
// K1: segment sums (best known: 4 replicas + depth-1 prefetch, ~5.1 TB/s).
// ---------------------------------------------------------------------------
__global__ __launch_bounds__(512) void k_segsum(const float4* __restrict__ E4,
                                                const int* __restrict__ labels,
                                                int nrows) {
    extern __shared__ float4 sm4[];            // [4][NC][D4]
    __shared__ int scnt[NC];
    const int g = threadIdx.x >> 7;
    const int t = threadIdx.x & 127;
    float4* rep = sm4 + g * (NC * D4);

    if (threadIdx.x < NC) scnt[threadIdx.x] = 0;
#pragma unroll
    for (int c = 0; c < NC; c++) rep[c * D4 + t] = make_float4(0.f, 0.f, 0.f, 0.f);
    __syncthreads();

    const int  gid    = blockIdx.x * 4 + g;
    const long stride = (long)SEG_GROUPS * 4;
    long r = (long)gid * 4;

    int4  lab = make_int4(0, 0, 0, 0);
    float4 v0, v1, v2, v3;
    bool have = (r + 4 <= nrows);
    if (have) {
        lab = *(const int4*)(labels + r);
        v0 = E4[(size_t)(r + 0) * D4 + t];
        v1 = E4[(size_t)(r + 1) * D4 + t];
        v2 = E4[(size_t)(r + 2) * D4 + t];
        v3 = E4[(size_t)(r + 3) * D4 + t];
    }
    while (have) {
        const long rn   = r + stride;
        const bool haven = (rn + 4 <= nrows);
        int4  labn = lab;
        float4 n0 = v0, n1 = v1, n2 = v2, n3 = v3;
        if (haven) {
            labn = *(const int4*)(labels + rn);
            n0 = E4[(size_t)(rn + 0) * D4 + t];
            n1 = E4[(size_t)(rn + 1) * D4 + t];
            n2 = E4[(size_t)(rn + 2) * D4 + t];
            n3 = E4[(size_t)(rn + 3) * D4 + t];
        }
        if (t == 0) {
            atomicAdd(&scnt[lab.x], 1); atomicAdd(&scnt[lab.y], 1);
            atomicAdd(&scnt[lab.z], 1); atomicAdd(&scnt[lab.w], 1);
        }
        float4* p;
        p = &rep[lab.x * D4 + t];
        { float4 a = *p; a.x += v0.x; a.y += v0.y; a.z += v0.z; a.w += v0.w; *p = a; }
        p = &rep[lab.y * D4 + t];
        { float4 a = *p; a.x += v1.x; a.y += v1.y; a.z += v1.z; a.w += v1.w; *p = a; }
        p = &rep[lab.z * D4 + t];
        { float4 a = *p; a.x += v2.x; a.y += v2.y; a.z += v2.z; a.w += v2.w; *p = a; }
        p = &rep[lab.w * D4 + t];
        { float4 a = *p; a.x += v3.x; a.y += v3.y; a.z += v3.z; a.w += v3.w; *p = a; }
        r = rn; have = haven;
        lab = labn; v0 = n0; v1 = n1; v2 = n2; v3 = n3;
    }
    if (r < nrows) {
        for (long rr = r; rr < nrows && rr < r + 4; rr++) {
            int lj = labels[rr];
            float4 v = E4[(size_t)rr * D4 + t];
            if (t == 0) atomicAdd(&scnt[lj], 1);
            float4* p = &rep[lj * D4 + t];
            float4 a = *p; a.x += v.x; a.y += v.y; a.z += v.z; a.w += v.w; *p = a;
        }
    }
    __syncthreads();

    for (int i = threadIdx.x; i < NC * D4; i += 512) {
        float4 a = sm4[i];
        float4 b = sm4[NC * D4 + i];
        float4 c = sm4[2 * NC * D4 + i];
        float4 d = sm4[3 * NC * D4 + i];
        a.x += b.x + c.x + d.x;
        a.y += b.y + c.y + d.y;
        a.z += b.z + c.z + d.z;
        a.w += b.w + c.w + d.w;
        g_part4[blockIdx.x * (NC * D4) + i] = a;
    }
    if (threadIdx.x < NC)
        g_cnt_part[blockIdx.x * NC + threadIdx.x] = scnt[threadIdx.x];
}

// ---------------------------------------------------------------------------
// K2: reduce partials -> g_sums4.
// ---------------------------------------------------------------------------
__global__ __launch_bounds__(128) void k_reduce() {
    const int i  = blockIdx.x * 32 + (threadIdx.x >> 2);
    const int ps = threadIdx.x & 3;
    float4 acc = make_float4(0.f, 0.f, 0.f, 0.f);
#pragma unroll 8
    for (int p = ps; p < SEG_BLOCKS; p += 4) {
        float4 v = g_part4[p * (NC * D4) + i];
        acc.x += v.x; acc.y += v.y; acc.z += v.z; acc.w += v.w;
    }
#pragma unroll
    for (int st = 1; st <= 2; st <<= 1) {
        acc.x += __shfl_xor_sync(0xFFFFFFFFu, acc.x, st);
        acc.y += __shfl_xor_sync(0xFFFFFFFFu, acc.y, st);
        acc.z += __shfl_xor_sync(0xFFFFFFFFu, acc.z, st);
        acc.w += __shfl_xor_sync(0xFFFFFFFFu, acc.w, st);
    }
    if (ps == 0) g_sums4[i] = acc;
}

// ---------------------------------------------------------------------------
// K3: counts -> prototypes -> ||p||^2 ; zero g_loss.
// ---------------------------------------------------------------------------
__global__ __launch_bounds__(512) void k_proto() {
    __shared__ float sinv[NC];
    const int tid = threadIdx.x, lane = tid & 31, w = tid >> 5;
    if (w < NC) {
        int s = 0;
        for (int p = lane; p < SEG_BLOCKS; p += 32) s += g_cnt_part[p * NC + w];
#pragma unroll
        for (int st = 16; st >= 1; st >>= 1) s += __shfl_xor_sync(0xFFFFFFFFu, s, st);
        if (lane == 0) sinv[w] = 1.0f / (float)s;
    }
    if (tid == 0) g_loss = 0.f;
    __syncthreads();
    const float* gs = (const float*)g_sums4;
    float*       gp = (float*)g_proto4;
#pragma unroll
    for (int c = 0; c < NC; c++) gp[c * DD + tid] = gs[c * DD + tid] * sinv[c];
    __syncthreads();
    if (w < NC) {
        const float* p = gp + w * DD;
        float acc = 0.f;
        for (int j = lane; j < DD; j += 32) acc = fmaf(p[j], p[j], acc);
#pragma unroll
        for (int st = 16; st >= 1; st >>= 1) acc += __shfl_xor_sync(0xFFFFFFFFu, acc, st);
        if (lane == 0) g_sqp[w] = acc;
    }
}

// ---------------------------------------------------------------------------
// K4: logits + log-softmax + loss.
// Lane layout per warp: lane = g*8 + ch*4 + dimq; 4 groups x 8 rows = 32
// rows/warp, 128 rows/block. 8 rows/group amortizes the 5 prototype LDS.128
// over 2KB of distinct gmem per iter: l1 cycles/iter = 8*4 + 5*4 = 52 ->
// cap 39 B/cyc/SM (~5.8 TB/s), up from R6's 4.2. Accums dot[8][5]+sq[8];
// __launch_bounds__(128,3) allows 170 regs (no spill), 12 warps/SM.
// Single clamped code path; 8-lane gmask shuffles only.
// ---------------------------------------------------------------------------
__global__ __launch_bounds__(128, 3) void k_logits(const float4* __restrict__ E4,
                                                   const int* __restrict__ labels,
                                                   float* __restrict__ out,
                                                   int nrows) {
    __shared__ float4 sp[NC * D4];   // 20 KB prototypes
    __shared__ float  ssqp[NC];
    __shared__ float  sloss;

    const int tid = threadIdx.x;
    for (int i = tid; i < NC * D4; i += 128) sp[i] = g_proto4[i];
    if (tid < NC) ssqp[tid] = g_sqp[tid];
    if (tid == 0) sloss = 0.f;
    __syncthreads();

    const int warp = tid >> 5;
    const int lane = tid & 31;
    const int dimq = lane & 3;
    const int ch   = (lane >> 2) & 1;
    const int g    = lane >> 3;
    const unsigned gmask = 0xFFu << (g * 8);
    const int r0   = blockIdx.x * 128 + warp * 32 + g * 8;

    // Clamped per-row pointers: loads always in-bounds, stores gated later.
    const ulonglong2* __restrict__ Ep[8];
#pragma unroll
    for (int j = 0; j < 8; j++) {
        int rc = r0 + j;
        if (rc > nrows - 1) rc = nrows - 1;
        Ep[j] = (const ulonglong2*)E4 + (size_t)rc * D4;
    }
    const ulonglong2* __restrict__ Pc =
        (const ulonglong2*)sp + (size_t)(ch * 5) * D4;

    ull dot[8][5];
#pragma unroll
    for (int j = 0; j < 8; j++)
#pragma unroll
        for (int c = 0; c < 5; c++) dot[j][c] = 0ull;
    ull sq[8];
#pragma unroll
    for (int j = 0; j < 8; j++) sq[j] = 0ull;

#pragma unroll 2
    for (int k = 0; k < 32; k++) {
        const int idx = k * 4 + dimq;
        ulonglong2 v[8];
#pragma unroll
        for (int j = 0; j < 8; j++) v[j] = Ep[j][idx];
#pragma unroll
        for (int j = 0; j < 8; j++) {
            sq[j] = fma2(v[j].x, v[j].x, sq[j]);
            sq[j] = fma2(v[j].y, v[j].y, sq[j]);
        }
#pragma unroll
        for (int c = 0; c < 5; c++) {
            ulonglong2 p = Pc[c * D4 + idx];
#pragma unroll
            for (int j = 0; j < 8; j++) {
                dot[j][c] = fma2(v[j].x, p.x, dot[j][c]);
                dot[j][c] = fma2(v[j].y, p.y, dot[j][c]);
            }
        }
    }

    // Epilogue per row (8-lane gmask shuffles; reconverged warp reduce after).
    float lvsum = 0.f;
#pragma unroll
    for (int j = 0; j < 8; j++) {
        const int  row   = r0 + j;
        const bool valid = (row < nrows);
        const int  rowc  = valid ? row : (nrows - 1);

        float sqe = u64_sum2(sq[j]);
        sqe += __shfl_xor_sync(gmask, sqe, 1);
        sqe += __shfl_xor_sync(gmask, sqe, 2);

        float l[5];
        float m5 = -1e30f;
#pragma unroll
        for (int c = 0; c < 5; c++) {
            float d = u64_sum2(dot[j][c]);
            d += __shfl_xor_sync(gmask, d, 1);
            d += __shfl_xor_sync(gmask, d, 2);
            float d2 = sqe + ssqp[ch * 5 + c] - 2.0f * d;
            float lg = -fmaxf(d2, 0.0f);
            l[c] = lg;
            m5 = fmaxf(m5, lg);
        }
        float m = fmaxf(m5, __shfl_xor_sync(gmask, m5, 4));
        float se5 = 0.f;
#pragma unroll
        for (int c = 0; c < 5; c++) se5 += __expf(l[c] - m);
        float se = se5 + __shfl_xor_sync(gmask, se5, 4);

        const int lab = labels[rowc];
        float lsel5 = 0.f;
#pragma unroll
        for (int c = 0; c < 5; c++)
            if (ch * 5 + c == lab) lsel5 = l[c];
        float lsel = lsel5 + __shfl_xor_sync(gmask, lsel5, 4);

        if (dimq == 0 && valid) {
            float* o = out + 1 + (size_t)rowc * NC + ch * 5;
#pragma unroll
            for (int c = 0; c < 5; c++) o[c] = l[c];
        }
        if (dimq == 0 && ch == 0 && valid)
            lvsum += m + __logf(se) - lsel;
    }

#pragma unroll
    for (int st = 16; st >= 1; st >>= 1)
        lvsum += __shfl_xor_sync(0xFFFFFFFFu, lvsum, st);
    if (lane == 0) atomicAdd(&sloss, lvsum);
    __syncthreads();
    if (tid == 0) atomicAdd(&g_loss, sloss);
}

// ---------------------------------------------------------------------------
// K5: finalize loss
// ---------------------------------------------------------------------------
__global__ void k_final(float* __restrict__ out, int nrows) {
    out[0] = g_loss * (1.0f / (float)nrows);
}

extern "C" void kernel_launch(void* const* d_in, const int* in_sizes, int n_in,
                              void* d_out, int out_size) {
    const float* E      = (const float*)d_in[0];
    const int*   labels = (const int*)d_in[1];
    float*       out    = (float*)d_out;
    const int nrows = in_sizes[1];   // 131072

    cudaFuncSetAttribute(k_segsum, cudaFuncAttributeMaxDynamicSharedMemorySize,
                         SEG_SMEM);

    k_segsum<<<SEG_BLOCKS, 512, SEG_SMEM>>>((const float4*)E, labels, nrows);
    k_reduce<<<40, 128>>>();
    k_proto<<<1, 512>>>();
    k_logits<<<(nrows + 127) / 128, 128>>>((const float4*)E, labels, out, nrows);
    k_final<<<1, 1>>>(out, nrows);
}

// round 12
// speedup vs baseline: 1.6407x; 1.2903x over previous
#include <cuda_runtime.h>
#include <cstdint>
#include <cstddef>

#define NC 10
#define DD 512
#define D4 128          // DD/4
#define SEG_BLOCKS 296
#define SEG_GROUPS (SEG_BLOCKS * 4)
#define SEG_SMEM (4 * NC * D4 * 16)   // 81920 bytes

typedef unsigned long long ull;

// Scratch (no cudaMalloc allowed)
__device__ float4 g_part4[SEG_BLOCKS * NC * D4];   // 6.06 MB partial sums
__device__ int    g_cnt_part[SEG_BLOCKS * NC];
__device__ float4 g_sums4[NC * D4];
__device__ float4 g_proto4[NC * D4];
__device__ float  g_sqp[NC];
__device__ float  g_loss;

static __device__ __forceinline__ ull fma2(ull a, ull b, ull c) {
    ull d;
    asm("fma.rn.f32x2 %0, %1, %2, %3;" : "=l"(d) : "l"(a), "l"(b), "l"(c));
    return d;
}
static __device__ __forceinline__ float u64_sum2(ull v) {
    float lo, hi;
    asm("mov.b64 {%0,%1}, %2;" : "=f"(lo), "=f"(hi) : "l"(v));
    return lo + hi;
}

// ---------------------------------------------------------------------------
// K1: segment sums (best known: 4 replicas + depth-1 prefetch, ~5.1 TB/s).
// Streams E FORWARD -> tail ~120MB of E stays L2-resident for k_logits.
// ---------------------------------------------------------------------------
__global__ __launch_bounds__(512) void k_segsum(const float4* __restrict__ E4,
                                                const int* __restrict__ labels,
                                                int nrows) {
    extern __shared__ float4 sm4[];            // [4][NC][D4]
    __shared__ int scnt[NC];
    const int g = threadIdx.x >> 7;
    const int t = threadIdx.x & 127;
    float4* rep = sm4 + g * (NC * D4);

    if (threadIdx.x < NC) scnt[threadIdx.x] = 0;
#pragma unroll
    for (int c = 0; c < NC; c++) rep[c * D4 + t] = make_float4(0.f, 0.f, 0.f, 0.f);
    __syncthreads();

    const int  gid    = blockIdx.x * 4 + g;
    const long stride = (long)SEG_GROUPS * 4;
    long r = (long)gid * 4;

    int4  lab = make_int4(0, 0, 0, 0);
    float4 v0, v1, v2, v3;
    bool have = (r + 4 <= nrows);
    if (have) {
        lab = *(const int4*)(labels + r);
        v0 = E4[(size_t)(r + 0) * D4 + t];
        v1 = E4[(size_t)(r + 1) * D4 + t];
        v2 = E4[(size_t)(r + 2) * D4 + t];
        v3 = E4[(size_t)(r + 3) * D4 + t];
    }
    while (have) {
        const long rn   = r + stride;
        const bool haven = (rn + 4 <= nrows);
        int4  labn = lab;
        float4 n0 = v0, n1 = v1, n2 = v2, n3 = v3;
        if (haven) {
            labn = *(const int4*)(labels + rn);
            n0 = E4[(size_t)(rn + 0) * D4 + t];
            n1 = E4[(size_t)(rn + 1) * D4 + t];
            n2 = E4[(size_t)(rn + 2) * D4 + t];
            n3 = E4[(size_t)(rn + 3) * D4 + t];
        }
        if (t == 0) {
            atomicAdd(&scnt[lab.x], 1); atomicAdd(&scnt[lab.y], 1);
            atomicAdd(&scnt[lab.z], 1); atomicAdd(&scnt[lab.w], 1);
        }
        float4* p;
        p = &rep[lab.x * D4 + t];
        { float4 a = *p; a.x += v0.x; a.y += v0.y; a.z += v0.z; a.w += v0.w; *p = a; }
        p = &rep[lab.y * D4 + t];
        { float4 a = *p; a.x += v1.x; a.y += v1.y; a.z += v1.z; a.w += v1.w; *p = a; }
        p = &rep[lab.z * D4 + t];
        { float4 a = *p; a.x += v2.x; a.y += v2.y; a.z += v2.z; a.w += v2.w; *p = a; }
        p = &rep[lab.w * D4 + t];
        { float4 a = *p; a.x += v3.x; a.y += v3.y; a.z += v3.z; a.w += v3.w; *p = a; }
        r = rn; have = haven;
        lab = labn; v0 = n0; v1 = n1; v2 = n2; v3 = n3;
    }
    if (r < nrows) {
        for (long rr = r; rr < nrows && rr < r + 4; rr++) {
            int lj = labels[rr];
            float4 v = E4[(size_t)rr * D4 + t];
            if (t == 0) atomicAdd(&scnt[lj], 1);
            float4* p = &rep[lj * D4 + t];
            float4 a = *p; a.x += v.x; a.y += v.y; a.z += v.z; a.w += v.w; *p = a;
        }
    }
    __syncthreads();

    for (int i = threadIdx.x; i < NC * D4; i += 512) {
        float4 a = sm4[i];
        float4 b = sm4[NC * D4 + i];
        float4 c = sm4[2 * NC * D4 + i];
        float4 d = sm4[3 * NC * D4 + i];
        a.x += b.x + c.x + d.x;
        a.y += b.y + c.y + d.y;
        a.z += b.z + c.z + d.z;
        a.w += b.w + c.w + d.w;
        g_part4[blockIdx.x * (NC * D4) + i] = a;
    }
    if (threadIdx.x < NC)
        g_cnt_part[blockIdx.x * NC + threadIdx.x] = scnt[threadIdx.x];
}

// ---------------------------------------------------------------------------
// K2: reduce partials -> g_sums4.
// ---------------------------------------------------------------------------
__global__ __launch_bounds__(128) void k_reduce() {
    const int i  = blockIdx.x * 32 + (threadIdx.x >> 2);
    const int ps = threadIdx.x & 3;
    float4 acc = make_float4(0.f, 0.f, 0.f, 0.f);
#pragma unroll 8
    for (int p = ps; p < SEG_BLOCKS; p += 4) {
        float4 v = g_part4[p * (NC * D4) + i];
        acc.x += v.x; acc.y += v.y; acc.z += v.z; acc.w += v.w;
    }
#pragma unroll
    for (int st = 1; st <= 2; st <<= 1) {
        acc.x += __shfl_xor_sync(0xFFFFFFFFu, acc.x, st);
        acc.y += __shfl_xor_sync(0xFFFFFFFFu, acc.y, st);
        acc.z += __shfl_xor_sync(0xFFFFFFFFu, acc.z, st);
        acc.w += __shfl_xor_sync(0xFFFFFFFFu, acc.w, st);
    }
    if (ps == 0) g_sums4[i] = acc;
}

// ---------------------------------------------------------------------------
// K3: counts -> prototypes -> ||p||^2 ; zero g_loss.
// ---------------------------------------------------------------------------
__global__ __launch_bounds__(512) void k_proto() {
    __shared__ float sinv[NC];
    const int tid = threadIdx.x, lane = tid & 31, w = tid >> 5;
    if (w < NC) {
        int s = 0;
        for (int p = lane; p < SEG_BLOCKS; p += 32) s += g_cnt_part[p * NC + w];
#pragma unroll
        for (int st = 16; st >= 1; st >>= 1) s += __shfl_xor_sync(0xFFFFFFFFu, s, st);
        if (lane == 0) sinv[w] = 1.0f / (float)s;
    }
    if (tid == 0) g_loss = 0.f;
    __syncthreads();
    const float* gs = (const float*)g_sums4;
    float*       gp = (float*)g_proto4;
#pragma unroll
    for (int c = 0; c < NC; c++) gp[c * DD + tid] = gs[c * DD + tid] * sinv[c];
    __syncthreads();
    if (w < NC) {
        const float* p = gp + w * DD;
        float acc = 0.f;
        for (int j = lane; j < DD; j += 32) acc = fmaf(p[j], p[j], acc);
#pragma unroll
        for (int st = 16; st >= 1; st >>= 1) acc += __shfl_xor_sync(0xFFFFFFFFu, acc, st);
        if (lane == 0) g_sqp[w] = acc;
    }
}

// ---------------------------------------------------------------------------
// K4: logits + log-softmax + loss. EXACT R6 mainloop (best measured: 84.5us,
// 3.26 TB/s) with ONE change: block->row mapping is REVERSED so the first
// scheduled blocks read the tail of E, which k_segsum just left L2-resident
// (~120MB). L2 hit: 240 vs 577 cyc -> higher effective MLP on ~45% of reads.
// Lane layout per warp: lane = g*8 + ch*4 + dimq; group g owns 4 rows.
// ---------------------------------------------------------------------------
__global__ __launch_bounds__(128, 5) void k_logits(const float4* __restrict__ E4,
                                                   const int* __restrict__ labels,
                                                   float* __restrict__ out,
                                                   int nrows) {
    __shared__ float4 sp[NC * D4];   // 20 KB prototypes
    __shared__ float  ssqp[NC];
    __shared__ float  sloss;

    for (int i = threadIdx.x; i < NC * D4; i += 128) sp[i] = g_proto4[i];
    if (threadIdx.x < NC) ssqp[threadIdx.x] = g_sqp[threadIdx.x];
    if (threadIdx.x == 0) sloss = 0.f;
    __syncthreads();

    const int warp = threadIdx.x >> 5;
    const int lane = threadIdx.x & 31;
    const int dimq = lane & 3;
    const int ch   = (lane >> 2) & 1;
    const int g    = lane >> 3;
    const unsigned gmask = 0xFFu << (g * 8);
    // Reversed mapping: early blocks (scheduled first) take the LAST rows.
    const int rblk = (int)gridDim.x - 1 - (int)blockIdx.x;
    const int r0   = rblk * 64 + warp * 16 + g * 4;

    // Clamped row indices: loads always in-bounds, stores gated by valid.
    int  rowc[4];
    bool valid[4];
#pragma unroll
    for (int j = 0; j < 4; j++) {
        int r = r0 + j;
        valid[j] = (r < nrows);
        rowc[j]  = valid[j] ? r : (nrows - 1);
    }

    const ulonglong2* __restrict__ Pp  = (const ulonglong2*)sp;
    const ulonglong2* __restrict__ Ep0 = (const ulonglong2*)E4 + (size_t)rowc[0] * D4;
    const ulonglong2* __restrict__ Ep1 = (const ulonglong2*)E4 + (size_t)rowc[1] * D4;
    const ulonglong2* __restrict__ Ep2 = (const ulonglong2*)E4 + (size_t)rowc[2] * D4;
    const ulonglong2* __restrict__ Ep3 = (const ulonglong2*)E4 + (size_t)rowc[3] * D4;
    const ulonglong2* __restrict__ Pc  = Pp + (size_t)(ch * 5) * D4;

    ull dot[4][5];
#pragma unroll
    for (int j = 0; j < 4; j++)
#pragma unroll
        for (int c = 0; c < 5; c++) dot[j][c] = 0ull;
    ull sq[4] = {0ull, 0ull, 0ull, 0ull};

#pragma unroll 2
    for (int k = 0; k < 32; k++) {
        const int idx = k * 4 + dimq;
        ulonglong2 v0 = Ep0[idx];
        ulonglong2 v1 = Ep1[idx];
        ulonglong2 v2 = Ep2[idx];
        ulonglong2 v3 = Ep3[idx];
        sq[0] = fma2(v0.x, v0.x, sq[0]); sq[0] = fma2(v0.y, v0.y, sq[0]);
        sq[1] = fma2(v1.x, v1.x, sq[1]); sq[1] = fma2(v1.y, v1.y, sq[1]);
        sq[2] = fma2(v2.x, v2.x, sq[2]); sq[2] = fma2(v2.y, v2.y, sq[2]);
        sq[3] = fma2(v3.x, v3.x, sq[3]); sq[3] = fma2(v3.y, v3.y, sq[3]);
#pragma unroll
        for (int c = 0; c < 5; c++) {
            ulonglong2 p = Pc[c * D4 + idx];
            dot[0][c] = fma2(v0.x, p.x, dot[0][c]); dot[0][c] = fma2(v0.y, p.y, dot[0][c]);
            dot[1][c] = fma2(v1.x, p.x, dot[1][c]); dot[1][c] = fma2(v1.y, p.y, dot[1][c]);
            dot[2][c] = fma2(v2.x, p.x, dot[2][c]); dot[2][c] = fma2(v2.y, p.y, dot[2][c]);
            dot[3][c] = fma2(v3.x, p.x, dot[3][c]); dot[3][c] = fma2(v3.y, p.y, dot[3][c]);
        }
    }

    float lvsum = 0.f;
#pragma unroll
    for (int j = 0; j < 4; j++) {
        float sqe = u64_sum2(sq[j]);
        sqe += __shfl_xor_sync(gmask, sqe, 1);
        sqe += __shfl_xor_sync(gmask, sqe, 2);

        float l[5];
        float m5 = -1e30f;
#pragma unroll
        for (int c = 0; c < 5; c++) {
            float d = u64_sum2(dot[j][c]);
            d += __shfl_xor_sync(gmask, d, 1);
            d += __shfl_xor_sync(gmask, d, 2);
            float d2 = sqe + ssqp[ch * 5 + c] - 2.0f * d;
            float lg = -fmaxf(d2, 0.0f);
            l[c] = lg;
            m5 = fmaxf(m5, lg);
        }
        float m = fmaxf(m5, __shfl_xor_sync(gmask, m5, 4));
        float se5 = 0.f;
#pragma unroll
        for (int c = 0; c < 5; c++) se5 += __expf(l[c] - m);
        float se = se5 + __shfl_xor_sync(gmask, se5, 4);

        const int lab = labels[rowc[j]];
        float lsel5 = 0.f;
#pragma unroll
        for (int c = 0; c < 5; c++)
            if (ch * 5 + c == lab) lsel5 = l[c];
        float lsel = lsel5 + __shfl_xor_sync(gmask, lsel5, 4);

        if (dimq == 0 && valid[j]) {
            float* o = out + 1 + (size_t)rowc[j] * NC + ch * 5;
#pragma unroll
            for (int c = 0; c < 5; c++) o[c] = l[c];
        }
        if (dimq == 0 && ch == 0 && valid[j])
            lvsum += m + __logf(se) - lsel;
    }

#pragma unroll
    for (int st = 16; st >= 1; st >>= 1)
        lvsum += __shfl_xor_sync(0xFFFFFFFFu, lvsum, st);
    if (lane == 0) atomicAdd(&sloss, lvsum);
    __syncthreads();
    if (threadIdx.x == 0) atomicAdd(&g_loss, sloss);
}

// ---------------------------------------------------------------------------
// K5: finalize loss
// ---------------------------------------------------------------------------
__global__ void k_final(float* __restrict__ out, int nrows) {
    out[0] = g_loss * (1.0f / (float)nrows);
}

extern "C" void kernel_launch(void* const* d_in, const int* in_sizes, int n_in,
                              void* d_out, int out_size) {
    const float* E      = (const float*)d_in[0];
    const int*   labels = (const int*)d_in[1];
    float*       out    = (float*)d_out;
    const int nrows = in_sizes[1];   // 131072

    cudaFuncSetAttribute(k_segsum, cudaFuncAttributeMaxDynamicSharedMemorySize,
                         SEG_SMEM);

    k_segsum<<<SEG_BLOCKS, 512, SEG_SMEM>>>((const float4*)E, labels, nrows);
    k_reduce<<<40, 128>>>();
    k_proto<<<1, 512>>>();
    k_logits<<<(nrows + 63) / 64, 128>>>((const float4*)E, labels, out, nrows);
    k_final<<<1, 1>>>(out, nrows);
}